// round 13
// baseline (speedup 1.0000x reference)
#include <cuda_runtime.h>
#include <math.h>

// Problem constants
#define CB   2
#define CS   2048
#define CD   1024
#define CH   16
#define CDK  64
#define BIAS_LEN (2*CS - 1)   // 4095 relative distances

typedef unsigned long long u64;

// ---------------- packed f32x2 helpers (sm_103a FFMA2 path) ----------------
__device__ __forceinline__ u64 pack2(float lo, float hi) {
    u64 r; asm("mov.b64 %0, {%1, %2};" : "=l"(r) : "f"(lo), "f"(hi)); return r;
}
__device__ __forceinline__ void unpack2(u64 v, float& lo, float& hi) {
    asm("mov.b64 {%0, %1}, %2;" : "=f"(lo), "=f"(hi) : "l"(v));
}
__device__ __forceinline__ void fma2(u64& d, u64 a, u64 b) {
    asm("fma.rn.f32x2 %0, %1, %2, %3;" : "=l"(d) : "l"(a), "l"(b), "l"(d));
}
__device__ __forceinline__ u64 mul2(u64 a, u64 b) {
    u64 r; asm("mul.rn.f32x2 %0, %1, %2;" : "=l"(r) : "l"(a), "l"(b)); return r;
}

// ---------------- scratch (static device globals; no runtime allocation) ----
__device__ __align__(16) float g_Q[(size_t)CB*CH*CS*CDK];
__device__ __align__(16) float g_K[(size_t)CB*CH*CS*CDK];
__device__ __align__(16) float g_V[(size_t)CB*CH*CS*CDK];
__device__ __align__(16) float g_AO[(size_t)CB*CS*CD];
__device__ __align__(16) float g_bias[CH*BIAS_LEN];

// ---------------- T5 relative position bias table --------------------------
__global__ void bias_table_kernel(const float* __restrict__ rel_bias)
{
    int idx = blockIdx.x * blockDim.x + threadIdx.x;
    if (idx >= CH * BIAS_LEN) return;
    int h = idx / BIAS_LEN;
    int t = idx - h * BIAS_LEN;
    int d = t - (CS - 1);

    int base = (d > 0) ? 16 : 0;
    int a = (d < 0) ? -d : d;
    int bucket;
    if (a < 8) {
        bucket = a;
    } else {
        float v = logf((float)a * 0.125f);
        v = v / 2.772588722239781f;     // ln(16)
        v = v * 8.0f;
        int bl = 8 + (int)v;
        bucket = (bl > 15) ? 15 : bl;
    }
    g_bias[h * BIAS_LEN + t] = rel_bias[(base + bucket) * CH + h];
}

// ---------------- SGEMM: 128x128 block, BK=8, 8x8 micro-tile, f32x2 --------
#define GBM 128
#define GBN 128
#define GBK 8

__device__ __forceinline__ void sgemm_body(
    const float* __restrict__ A, const float* __restrict__ W,
    float* __restrict__ C, int N, int K, int scatter)
{
    __shared__ float Asd[GBK][2*GBM];   // A duplicated: Asd[k][2r]=Asd[k][2r+1]
    __shared__ float Bs[GBK][GBN];
    const int tid = threadIdx.x;        // 256 threads
    const int tx = tid & 15;
    const int ty = tid >> 4;
    const float* Ab = A + (size_t)blockIdx.y * GBM * K;
    const float* Wb = W + blockIdx.x * GBN;

    u64 acc[8][4];                      // pairs along j: cols 8tx+2j2, 8tx+2j2+1
    #pragma unroll
    for (int i = 0; i < 8; i++)
        #pragma unroll
        for (int j = 0; j < 4; j++) acc[i][j] = 0ULL;

    const int aRow = tid >> 1;          // 0..127
    const int aCol = (tid & 1) << 2;    // 0 or 4
    const int bRow = tid >> 5;          // 0..7
    const int bCol = (tid & 31) << 2;   // 0..124

    for (int k0 = 0; k0 < K; k0 += GBK) {
        float4 a4 = *(const float4*)(Ab + (size_t)aRow * K + k0 + aCol);
        *(u64*)&Asd[aCol + 0][2*aRow] = pack2(a4.x, a4.x);
        *(u64*)&Asd[aCol + 1][2*aRow] = pack2(a4.y, a4.y);
        *(u64*)&Asd[aCol + 2][2*aRow] = pack2(a4.z, a4.z);
        *(u64*)&Asd[aCol + 3][2*aRow] = pack2(a4.w, a4.w);
        *(float4*)(&Bs[bRow][bCol]) =
            *(const float4*)(Wb + (size_t)(k0 + bRow) * N + bCol);
        __syncthreads();
        #pragma unroll
        for (int kk = 0; kk < GBK; kk++) {
            const ulonglong2* ap = (const ulonglong2*)&Asd[kk][16 * ty];
            ulonglong2 a01 = ap[0], a23 = ap[1], a45 = ap[2], a67 = ap[3];
            const ulonglong2* bp = (const ulonglong2*)&Bs[kk][8 * tx];
            ulonglong2 b01 = bp[0], b23 = bp[1];
            u64 ar[8] = {a01.x, a01.y, a23.x, a23.y, a45.x, a45.y, a67.x, a67.y};
            u64 br[4] = {b01.x, b01.y, b23.x, b23.y};
            #pragma unroll
            for (int i = 0; i < 8; i++)
                #pragma unroll
                for (int j = 0; j < 4; j++)
                    fma2(acc[i][j], ar[i], br[j]);
        }
        __syncthreads();
    }

    #pragma unroll
    for (int i = 0; i < 8; i++) {
        float c[8];
        unpack2(acc[i][0], c[0], c[1]);
        unpack2(acc[i][1], c[2], c[3]);
        unpack2(acc[i][2], c[4], c[5]);
        unpack2(acc[i][3], c[6], c[7]);
        int m = blockIdx.y * GBM + ty * 8 + i;
        float* Crow;
        if (!scatter) {
            Crow = C + (size_t)m * N + blockIdx.x * GBN + tx * 8;
        } else {
            int b = m >> 11;
            int s = m & (CS - 1);
            int n = blockIdx.x * GBN + tx * 8;   // 8 cols stay inside one head
            int h = n >> 6;
            int dk = n & 63;
            Crow = C + ((((size_t)b * CH + h) * CS + s) * CDK + dk);
        }
        *(float4*)(Crow)     = make_float4(c[0], c[1], c[2], c[3]);
        *(float4*)(Crow + 4) = make_float4(c[4], c[5], c[6], c[7]);
    }
}

__global__ void __launch_bounds__(256) qkv_kernel(
    const float* __restrict__ X,
    const float* __restrict__ Wq, const float* __restrict__ Wk,
    const float* __restrict__ Wv)
{
    const float* W = (blockIdx.z == 0) ? Wq : (blockIdx.z == 1) ? Wk : Wv;
    float* O = (blockIdx.z == 0) ? g_Q : (blockIdx.z == 1) ? g_K : g_V;
    sgemm_body(X, W, O, CD, CD, 1);
}

__global__ void __launch_bounds__(256) out_proj_kernel(
    const float* __restrict__ Wo, float* __restrict__ out)
{
    sgemm_body(g_AO, Wo, out, CD, CD, 0);
}

// ---------------- fused flash attention (fp32, f32x2, online softmax) ------
#define AQ  64          // q rows per block
#define AK  64          // k rows per tile
#define ALD 68          // padded smem row for Ks/Vs
#define DLD 132         // padded row for duplicated Qsd/Psd (2*64 + 4)

struct AttnSmem {
    float Qsd[CDK][DLD];  // duplicated Q transposed: Qsd[d][2r]=Qsd[d][2r+1]
    float Ks[CDK][ALD];   // K transposed: Ks[d][c]
    float Vs[AK][ALD];    // Vs[kk][d]
    float Psd[AQ][DLD];   // duplicated probabilities: Psd[r][2kk]=Psd[r][2kk+1]
    float bias[CS + AQ];  // bias slice for this q-tile
};

__global__ void __launch_bounds__(256) attn_kernel()
{
    extern __shared__ char smem_raw[];
    AttnSmem* sm = reinterpret_cast<AttnSmem*>(smem_raw);

    const int tid = threadIdx.x;       // 256 threads: 16x16, 4x4 micro-tiles
    const int tx = tid & 15;
    const int ty = tid >> 4;
    const int i0 = blockIdx.x * AQ;
    const int h  = blockIdx.y;
    const int b  = blockIdx.z;

    const size_t head_off = ((size_t)b * CH + h) * CS * CDK;
    const float* Qg = g_Q + head_off + (size_t)i0 * CDK;
    const float* Kg = g_K + head_off;
    const float* Vg = g_V + head_off;

    // load Q tile transposed + duplicated: Qsd[d][2r],[2r+1]
    for (int v = tid; v < AQ * (CDK / 4); v += 256) {
        int r  = v >> 4;
        int d4 = (v & 15) << 2;
        float4 q4 = *(const float4*)(Qg + r * CDK + d4);
        *(u64*)&sm->Qsd[d4 + 0][2*r] = pack2(q4.x, q4.x);
        *(u64*)&sm->Qsd[d4 + 1][2*r] = pack2(q4.y, q4.y);
        *(u64*)&sm->Qsd[d4 + 2][2*r] = pack2(q4.z, q4.z);
        *(u64*)&sm->Qsd[d4 + 3][2*r] = pack2(q4.w, q4.w);
    }
    // load bias slice (same indexing as the passing round-10 kernel)
    for (int t = tid; t < CS - 1 + AQ; t += 256)
        sm->bias[t] = g_bias[h * BIAS_LEN + t + CS - i0 - AQ];

    float m[4], l[4];
    u64 o2[4][2];                       // o pairs along j: cols 4tx+2j2, +1
    #pragma unroll
    for (int i = 0; i < 4; i++) {
        m[i] = -1e30f;
        l[i] = 0.f;
        o2[i][0] = 0ULL; o2[i][1] = 0ULL;
    }

    for (int kt = 0; kt < CS / AK; kt++) {
        const int kj0 = kt * AK;
        __syncthreads();   // prev-iter PV done with Psd/Vs

        // load K (transposed) + V tiles
        for (int v = tid; v < AK * (CDK / 4); v += 256) {
            int row = v >> 4;
            int d4  = (v & 15) << 2;
            float4 k4 = *(const float4*)(Kg + (size_t)(kj0 + row) * CDK + d4);
            sm->Ks[d4 + 0][row] = k4.x;
            sm->Ks[d4 + 1][row] = k4.y;
            sm->Ks[d4 + 2][row] = k4.z;
            sm->Ks[d4 + 3][row] = k4.w;
            *(float4*)&sm->Vs[row][d4] =
                *(const float4*)(Vg + (size_t)(kj0 + row) * CDK + d4);
        }
        __syncthreads();

        // S = Q @ K^T  -- f32x2, pairs along j (K naturally paired)
        u64 s2[4][2];
        #pragma unroll
        for (int i = 0; i < 4; i++) { s2[i][0] = 0ULL; s2[i][1] = 0ULL; }

        #pragma unroll 8
        for (int d = 0; d < CDK; d++) {
            const ulonglong2 q01 = *(const ulonglong2*)&sm->Qsd[d][8 * ty];
            const ulonglong2 q23 = *(const ulonglong2*)&sm->Qsd[d][8 * ty + 4];
            const ulonglong2 kk2 = *(const ulonglong2*)&sm->Ks[d][4 * tx];
            u64 qd[4] = {q01.x, q01.y, q23.x, q23.y};
            #pragma unroll
            for (int i = 0; i < 4; i++) {
                fma2(s2[i][0], qd[i], kk2.x);
                fma2(s2[i][1], qd[i], kk2.y);
            }
        }

        // unpack scores
        float s[4][4];
        #pragma unroll
        for (int i = 0; i < 4; i++) {
            unpack2(s2[i][0], s[i][0], s[i][1]);
            unpack2(s2[i][1], s[i][2], s[i][3]);
        }

        // + position bias (T5: no 1/sqrt(dk) scaling)
        #pragma unroll
        for (int i = 0; i < 4; i++) {
            int tb = kj0 + tx * 4 + (AQ - 1) - (ty * 4 + i);
            #pragma unroll
            for (int j = 0; j < 4; j++)
                s[i][j] += sm->bias[tb + j];
        }

        // online softmax: rows owned by 16 lanes with same ty
        #pragma unroll
        for (int i = 0; i < 4; i++) {
            float mloc = fmaxf(fmaxf(s[i][0], s[i][1]), fmaxf(s[i][2], s[i][3]));
            #pragma unroll
            for (int off = 8; off >= 1; off >>= 1)
                mloc = fmaxf(mloc, __shfl_xor_sync(0xffffffffu, mloc, off));
            float mnew = fmaxf(m[i], mloc);
            float sc = __expf(m[i] - mnew);
            m[i] = mnew;
            float ps = 0.f;
            #pragma unroll
            for (int j = 0; j < 4; j++) {
                float p = __expf(s[i][j] - mnew);
                s[i][j] = p;
                ps += p;
            }
            #pragma unroll
            for (int off = 8; off >= 1; off >>= 1)
                ps += __shfl_xor_sync(0xffffffffu, ps, off);
            l[i] = l[i] * sc + ps;
            u64 sc2 = pack2(sc, sc);
            o2[i][0] = mul2(o2[i][0], sc2);
            o2[i][1] = mul2(o2[i][1], sc2);
        }

        // stash probabilities duplicated: Psd[r][2k]=Psd[r][2k+1]=p
        #pragma unroll
        for (int i = 0; i < 4; i++) {
            *(float4*)&sm->Psd[ty * 4 + i][8 * tx] =
                make_float4(s[i][0], s[i][0], s[i][1], s[i][1]);
            *(float4*)&sm->Psd[ty * 4 + i][8 * tx + 4] =
                make_float4(s[i][2], s[i][2], s[i][3], s[i][3]);
        }
        __syncthreads();

        // O += P @ V  -- f32x2, V naturally paired, P broadcast via dup LDS.64
        #pragma unroll 8
        for (int kk = 0; kk < AK; kk++) {
            const ulonglong2 v2 = *(const ulonglong2*)&sm->Vs[kk][4 * tx];
            u64 p0 = *(const u64*)&sm->Psd[ty * 4 + 0][2 * kk];
            u64 p1 = *(const u64*)&sm->Psd[ty * 4 + 1][2 * kk];
            u64 p2 = *(const u64*)&sm->Psd[ty * 4 + 2][2 * kk];
            u64 p3 = *(const u64*)&sm->Psd[ty * 4 + 3][2 * kk];
            fma2(o2[0][0], p0, v2.x); fma2(o2[0][1], p0, v2.y);
            fma2(o2[1][0], p1, v2.x); fma2(o2[1][1], p1, v2.y);
            fma2(o2[2][0], p2, v2.x); fma2(o2[2][1], p2, v2.y);
            fma2(o2[3][0], p3, v2.x); fma2(o2[3][1], p3, v2.y);
        }
    }

    // epilogue: normalize, write [b, s, h*64+dk] (ready for Wo GEMM)
    #pragma unroll
    for (int i = 0; i < 4; i++) {
        float inv = 1.f / l[i];
        float o0, o1, o2v, o3;
        unpack2(o2[i][0], o0, o1);
        unpack2(o2[i][1], o2v, o3);
        int srow = i0 + ty * 4 + i;
        float* dst = g_AO + ((size_t)b * CS + srow) * CD + h * CDK + tx * 4;
        *(float4*)dst = make_float4(o0 * inv, o1 * inv, o2v * inv, o3 * inv);
    }
}

// ---------------- launch ----------------------------------------------------
extern "C" void kernel_launch(void* const* d_in, const int* in_sizes, int n_in,
                              void* d_out, int out_size)
{
    (void)in_sizes; (void)n_in; (void)out_size;
    const float* X  = (const float*)d_in[0];
    const float* Wq = (const float*)d_in[1];
    const float* Wk = (const float*)d_in[2];
    const float* Wv = (const float*)d_in[3];
    const float* Wo = (const float*)d_in[4];
    const float* rb = (const float*)d_in[5];
    float* out = (float*)d_out;

    // 1) relative-position bias table
    {
        int total = CH * BIAS_LEN;
        bias_table_kernel<<<(total + 255) / 256, 256>>>(rb);
    }
    // 2) fused QKV projections
    {
        dim3 grid(CD / GBN, (CB * CS) / GBM, 3);
        qkv_kernel<<<grid, 256>>>(X, Wq, Wk, Wv);
    }
    // 3) fused flash attention
    {
        cudaFuncSetAttribute(attn_kernel,
                             cudaFuncAttributeMaxDynamicSharedMemorySize,
                             (int)sizeof(AttnSmem));
        dim3 grid(CS / AQ, CH, CB);
        attn_kernel<<<grid, 256, sizeof(AttnSmem)>>>();
    }
    // 4) output projection -> d_out
    {
        dim3 grid(CD / GBN, (CB * CS) / GBM);
        out_proj_kernel<<<grid, 256>>>(Wo, out);
    }
}

// round 14
// speedup vs baseline: 1.0005x; 1.0005x over previous
#include <cuda_runtime.h>
#include <math.h>

// Problem constants
#define CB   2
#define CS   2048
#define CD   1024
#define CH   16
#define CDK  64
#define BIAS_LEN (2*CS - 1)   // 4095 relative distances

typedef unsigned long long u64;

// ---------------- packed f32x2 helpers (sm_103a FFMA2 path) ----------------
__device__ __forceinline__ u64 pack2(float lo, float hi) {
    u64 r; asm("mov.b64 %0, {%1, %2};" : "=l"(r) : "f"(lo), "f"(hi)); return r;
}
__device__ __forceinline__ void unpack2(u64 v, float& lo, float& hi) {
    asm("mov.b64 {%0, %1}, %2;" : "=f"(lo), "=f"(hi) : "l"(v));
}
__device__ __forceinline__ void fma2(u64& d, u64 a, u64 b) {
    asm("fma.rn.f32x2 %0, %1, %2, %3;" : "=l"(d) : "l"(a), "l"(b), "l"(d));
}
__device__ __forceinline__ u64 mul2(u64 a, u64 b) {
    u64 r; asm("mul.rn.f32x2 %0, %1, %2;" : "=l"(r) : "l"(a), "l"(b)); return r;
}

// ---------------- scratch (static device globals; no runtime allocation) ----
__device__ __align__(16) float g_Q[(size_t)CB*CH*CS*CDK];
__device__ __align__(16) float g_K[(size_t)CB*CH*CS*CDK];
__device__ __align__(16) float g_V[(size_t)CB*CH*CS*CDK];
__device__ __align__(16) float g_AO[(size_t)CB*CS*CD];
__device__ __align__(16) float g_bias[CH*BIAS_LEN];

// ---------------- T5 relative position bias table --------------------------
__global__ void bias_table_kernel(const float* __restrict__ rel_bias)
{
    int idx = blockIdx.x * blockDim.x + threadIdx.x;
    if (idx >= CH * BIAS_LEN) return;
    int h = idx / BIAS_LEN;
    int t = idx - h * BIAS_LEN;
    int d = t - (CS - 1);

    int base = (d > 0) ? 16 : 0;
    int a = (d < 0) ? -d : d;
    int bucket;
    if (a < 8) {
        bucket = a;
    } else {
        float v = logf((float)a * 0.125f);
        v = v / 2.772588722239781f;     // ln(16)
        v = v * 8.0f;
        int bl = 8 + (int)v;
        bucket = (bl > 15) ? 15 : bl;
    }
    g_bias[h * BIAS_LEN + t] = rel_bias[(base + bucket) * CH + h];
}

// ---------------- SGEMM: 128x128 block, BK=8, 8x8 micro-tile, f32x2 --------
#define GBM 128
#define GBN 128
#define GBK 8

__device__ __forceinline__ void sgemm_body(
    const float* __restrict__ A, const float* __restrict__ W,
    float* __restrict__ C, int N, int K, int scatter)
{
    __shared__ float Asd[GBK][2*GBM];   // A duplicated: Asd[k][2r]=Asd[k][2r+1]
    __shared__ float Bs[GBK][GBN];
    const int tid = threadIdx.x;        // 256 threads
    const int tx = tid & 15;
    const int ty = tid >> 4;
    const float* Ab = A + (size_t)blockIdx.y * GBM * K;
    const float* Wb = W + blockIdx.x * GBN;

    u64 acc[8][4];                      // pairs along j: cols 8tx+2j2, 8tx+2j2+1
    #pragma unroll
    for (int i = 0; i < 8; i++)
        #pragma unroll
        for (int j = 0; j < 4; j++) acc[i][j] = 0ULL;

    const int aRow = tid >> 1;          // 0..127
    const int aCol = (tid & 1) << 2;    // 0 or 4
    const int bRow = tid >> 5;          // 0..7
    const int bCol = (tid & 31) << 2;   // 0..124

    for (int k0 = 0; k0 < K; k0 += GBK) {
        float4 a4 = *(const float4*)(Ab + (size_t)aRow * K + k0 + aCol);
        *(u64*)&Asd[aCol + 0][2*aRow] = pack2(a4.x, a4.x);
        *(u64*)&Asd[aCol + 1][2*aRow] = pack2(a4.y, a4.y);
        *(u64*)&Asd[aCol + 2][2*aRow] = pack2(a4.z, a4.z);
        *(u64*)&Asd[aCol + 3][2*aRow] = pack2(a4.w, a4.w);
        *(float4*)(&Bs[bRow][bCol]) =
            *(const float4*)(Wb + (size_t)(k0 + bRow) * N + bCol);
        __syncthreads();
        #pragma unroll
        for (int kk = 0; kk < GBK; kk++) {
            const ulonglong2* ap = (const ulonglong2*)&Asd[kk][16 * ty];
            ulonglong2 a01 = ap[0], a23 = ap[1], a45 = ap[2], a67 = ap[3];
            const ulonglong2* bp = (const ulonglong2*)&Bs[kk][8 * tx];
            ulonglong2 b01 = bp[0], b23 = bp[1];
            u64 ar[8] = {a01.x, a01.y, a23.x, a23.y, a45.x, a45.y, a67.x, a67.y};
            u64 br[4] = {b01.x, b01.y, b23.x, b23.y};
            #pragma unroll
            for (int i = 0; i < 8; i++)
                #pragma unroll
                for (int j = 0; j < 4; j++)
                    fma2(acc[i][j], ar[i], br[j]);
        }
        __syncthreads();
    }

    #pragma unroll
    for (int i = 0; i < 8; i++) {
        float c[8];
        unpack2(acc[i][0], c[0], c[1]);
        unpack2(acc[i][1], c[2], c[3]);
        unpack2(acc[i][2], c[4], c[5]);
        unpack2(acc[i][3], c[6], c[7]);
        int m = blockIdx.y * GBM + ty * 8 + i;
        float* Crow;
        if (!scatter) {
            Crow = C + (size_t)m * N + blockIdx.x * GBN + tx * 8;
        } else {
            int b = m >> 11;
            int s = m & (CS - 1);
            int n = blockIdx.x * GBN + tx * 8;   // 8 cols stay inside one head
            int h = n >> 6;
            int dk = n & 63;
            Crow = C + ((((size_t)b * CH + h) * CS + s) * CDK + dk);
        }
        *(float4*)(Crow)     = make_float4(c[0], c[1], c[2], c[3]);
        *(float4*)(Crow + 4) = make_float4(c[4], c[5], c[6], c[7]);
    }
}

__global__ void __launch_bounds__(256) qkv_kernel(
    const float* __restrict__ X,
    const float* __restrict__ Wq, const float* __restrict__ Wk,
    const float* __restrict__ Wv)
{
    const float* W = (blockIdx.z == 0) ? Wq : (blockIdx.z == 1) ? Wk : Wv;
    float* O = (blockIdx.z == 0) ? g_Q : (blockIdx.z == 1) ? g_K : g_V;
    sgemm_body(X, W, O, CD, CD, 1);
}

__global__ void __launch_bounds__(256) out_proj_kernel(
    const float* __restrict__ Wo, float* __restrict__ out)
{
    sgemm_body(g_AO, Wo, out, CD, CD, 0);
}

// ---------------- fused flash attention (fp32, f32x2, online softmax) ------
#define AQ  64          // q rows per block
#define AK  64          // k rows per tile
#define ALD 68          // padded smem row for Ks/Vs
#define DLD 132         // padded row for duplicated Qsd/Psd (2*64 + 4)

struct AttnSmem {
    float Qsd[CDK][DLD];  // duplicated Q transposed: Qsd[d][2r]=Qsd[d][2r+1]
    float Ks[CDK][ALD];   // K transposed: Ks[d][c]
    float Vs[AK][ALD];    // Vs[kk][d]
    float Psd[AQ][DLD];   // duplicated probabilities: Psd[r][2kk]=Psd[r][2kk+1]
    float bias[CS + AQ];  // bias slice for this q-tile
};

__global__ void __launch_bounds__(256) attn_kernel()
{
    extern __shared__ char smem_raw[];
    AttnSmem* sm = reinterpret_cast<AttnSmem*>(smem_raw);

    const int tid = threadIdx.x;       // 256 threads: 16x16, 4x4 micro-tiles
    const int tx = tid & 15;
    const int ty = tid >> 4;
    const int i0 = blockIdx.x * AQ;
    const int h  = blockIdx.y;
    const int b  = blockIdx.z;

    const size_t head_off = ((size_t)b * CH + h) * CS * CDK;
    const float* Qg = g_Q + head_off + (size_t)i0 * CDK;
    const float* Kg = g_K + head_off;
    const float* Vg = g_V + head_off;

    // load Q tile transposed + duplicated: Qsd[d][2r],[2r+1]
    for (int v = tid; v < AQ * (CDK / 4); v += 256) {
        int r  = v >> 4;
        int d4 = (v & 15) << 2;
        float4 q4 = *(const float4*)(Qg + r * CDK + d4);
        *(u64*)&sm->Qsd[d4 + 0][2*r] = pack2(q4.x, q4.x);
        *(u64*)&sm->Qsd[d4 + 1][2*r] = pack2(q4.y, q4.y);
        *(u64*)&sm->Qsd[d4 + 2][2*r] = pack2(q4.z, q4.z);
        *(u64*)&sm->Qsd[d4 + 3][2*r] = pack2(q4.w, q4.w);
    }
    // load bias slice (same indexing as the passing round-10 kernel)
    for (int t = tid; t < CS - 1 + AQ; t += 256)
        sm->bias[t] = g_bias[h * BIAS_LEN + t + CS - i0 - AQ];

    float m[4], l[4];
    u64 o2[4][2];                       // o pairs along j: cols 4tx+2j2, +1
    #pragma unroll
    for (int i = 0; i < 4; i++) {
        m[i] = -1e30f;
        l[i] = 0.f;
        o2[i][0] = 0ULL; o2[i][1] = 0ULL;
    }

    for (int kt = 0; kt < CS / AK; kt++) {
        const int kj0 = kt * AK;
        __syncthreads();   // prev-iter PV done with Psd/Vs

        // load K (transposed) + V tiles
        for (int v = tid; v < AK * (CDK / 4); v += 256) {
            int row = v >> 4;
            int d4  = (v & 15) << 2;
            float4 k4 = *(const float4*)(Kg + (size_t)(kj0 + row) * CDK + d4);
            sm->Ks[d4 + 0][row] = k4.x;
            sm->Ks[d4 + 1][row] = k4.y;
            sm->Ks[d4 + 2][row] = k4.z;
            sm->Ks[d4 + 3][row] = k4.w;
            *(float4*)&sm->Vs[row][d4] =
                *(const float4*)(Vg + (size_t)(kj0 + row) * CDK + d4);
        }
        __syncthreads();

        // S = Q @ K^T  -- f32x2, pairs along j (K naturally paired)
        u64 s2[4][2];
        #pragma unroll
        for (int i = 0; i < 4; i++) { s2[i][0] = 0ULL; s2[i][1] = 0ULL; }

        #pragma unroll 8
        for (int d = 0; d < CDK; d++) {
            const ulonglong2 q01 = *(const ulonglong2*)&sm->Qsd[d][8 * ty];
            const ulonglong2 q23 = *(const ulonglong2*)&sm->Qsd[d][8 * ty + 4];
            const ulonglong2 kk2 = *(const ulonglong2*)&sm->Ks[d][4 * tx];
            u64 qd[4] = {q01.x, q01.y, q23.x, q23.y};
            #pragma unroll
            for (int i = 0; i < 4; i++) {
                fma2(s2[i][0], qd[i], kk2.x);
                fma2(s2[i][1], qd[i], kk2.y);
            }
        }

        // unpack scores
        float s[4][4];
        #pragma unroll
        for (int i = 0; i < 4; i++) {
            unpack2(s2[i][0], s[i][0], s[i][1]);
            unpack2(s2[i][1], s[i][2], s[i][3]);
        }

        // + position bias (T5: no 1/sqrt(dk) scaling)
        #pragma unroll
        for (int i = 0; i < 4; i++) {
            int tb = kj0 + tx * 4 + (AQ - 1) - (ty * 4 + i);
            #pragma unroll
            for (int j = 0; j < 4; j++)
                s[i][j] += sm->bias[tb + j];
        }

        // online softmax: rows owned by 16 lanes with same ty
        #pragma unroll
        for (int i = 0; i < 4; i++) {
            float mloc = fmaxf(fmaxf(s[i][0], s[i][1]), fmaxf(s[i][2], s[i][3]));
            #pragma unroll
            for (int off = 8; off >= 1; off >>= 1)
                mloc = fmaxf(mloc, __shfl_xor_sync(0xffffffffu, mloc, off));
            float mnew = fmaxf(m[i], mloc);
            float sc = __expf(m[i] - mnew);
            m[i] = mnew;
            float ps = 0.f;
            #pragma unroll
            for (int j = 0; j < 4; j++) {
                float p = __expf(s[i][j] - mnew);
                s[i][j] = p;
                ps += p;
            }
            #pragma unroll
            for (int off = 8; off >= 1; off >>= 1)
                ps += __shfl_xor_sync(0xffffffffu, ps, off);
            l[i] = l[i] * sc + ps;
            u64 sc2 = pack2(sc, sc);
            o2[i][0] = mul2(o2[i][0], sc2);
            o2[i][1] = mul2(o2[i][1], sc2);
        }

        // stash probabilities duplicated: Psd[r][2k]=Psd[r][2k+1]=p
        #pragma unroll
        for (int i = 0; i < 4; i++) {
            *(float4*)&sm->Psd[ty * 4 + i][8 * tx] =
                make_float4(s[i][0], s[i][0], s[i][1], s[i][1]);
            *(float4*)&sm->Psd[ty * 4 + i][8 * tx + 4] =
                make_float4(s[i][2], s[i][2], s[i][3], s[i][3]);
        }
        __syncthreads();

        // O += P @ V  -- f32x2, V naturally paired, P broadcast via dup LDS.64
        #pragma unroll 8
        for (int kk = 0; kk < AK; kk++) {
            const ulonglong2 v2 = *(const ulonglong2*)&sm->Vs[kk][4 * tx];
            u64 p0 = *(const u64*)&sm->Psd[ty * 4 + 0][2 * kk];
            u64 p1 = *(const u64*)&sm->Psd[ty * 4 + 1][2 * kk];
            u64 p2 = *(const u64*)&sm->Psd[ty * 4 + 2][2 * kk];
            u64 p3 = *(const u64*)&sm->Psd[ty * 4 + 3][2 * kk];
            fma2(o2[0][0], p0, v2.x); fma2(o2[0][1], p0, v2.y);
            fma2(o2[1][0], p1, v2.x); fma2(o2[1][1], p1, v2.y);
            fma2(o2[2][0], p2, v2.x); fma2(o2[2][1], p2, v2.y);
            fma2(o2[3][0], p3, v2.x); fma2(o2[3][1], p3, v2.y);
        }
    }

    // epilogue: normalize, write [b, s, h*64+dk] (ready for Wo GEMM)
    #pragma unroll
    for (int i = 0; i < 4; i++) {
        float inv = 1.f / l[i];
        float o0, o1, o2v, o3;
        unpack2(o2[i][0], o0, o1);
        unpack2(o2[i][1], o2v, o3);
        int srow = i0 + ty * 4 + i;
        float* dst = g_AO + ((size_t)b * CS + srow) * CD + h * CDK + tx * 4;
        *(float4*)dst = make_float4(o0 * inv, o1 * inv, o2v * inv, o3 * inv);
    }
}

// ---------------- launch ----------------------------------------------------
extern "C" void kernel_launch(void* const* d_in, const int* in_sizes, int n_in,
                              void* d_out, int out_size)
{
    (void)in_sizes; (void)n_in; (void)out_size;
    const float* X  = (const float*)d_in[0];
    const float* Wq = (const float*)d_in[1];
    const float* Wk = (const float*)d_in[2];
    const float* Wv = (const float*)d_in[3];
    const float* Wo = (const float*)d_in[4];
    const float* rb = (const float*)d_in[5];
    float* out = (float*)d_out;

    // 1) relative-position bias table
    {
        int total = CH * BIAS_LEN;
        bias_table_kernel<<<(total + 255) / 256, 256>>>(rb);
    }
    // 2) fused QKV projections
    {
        dim3 grid(CD / GBN, (CB * CS) / GBM, 3);
        qkv_kernel<<<grid, 256>>>(X, Wq, Wk, Wv);
    }
    // 3) fused flash attention
    {
        cudaFuncSetAttribute(attn_kernel,
                             cudaFuncAttributeMaxDynamicSharedMemorySize,
                             (int)sizeof(AttnSmem));
        dim3 grid(CS / AQ, CH, CB);
        attn_kernel<<<grid, 256, sizeof(AttnSmem)>>>();
    }
    // 4) output projection -> d_out
    {
        dim3 grid(CD / GBN, (CB * CS) / GBM);
        out_proj_kernel<<<grid, 256>>>(Wo, out);
    }
}

// round 15
// speedup vs baseline: 3.0941x; 3.0925x over previous
#include <cuda_runtime.h>
#include <cuda_bf16.h>
#include <math.h>
#include <stdint.h>

// Problem constants
#define CB   2
#define CS   2048
#define CD   1024
#define CH   16
#define CDK  64
#define BIAS_LEN (2*CS - 1)   // 4095 relative distances

// ---------------- scratch (static device globals; no runtime allocation) ----
__device__ __align__(16) float g_Q[(size_t)CB*CH*CS*CDK];
__device__ __align__(16) float g_K[(size_t)CB*CH*CS*CDK];
__device__ __align__(16) float g_V[(size_t)CB*CH*CS*CDK];
__device__ __align__(16) float g_AO[(size_t)CB*CS*CD];
__device__ __align__(16) float g_bias[CH*BIAS_LEN];

// ---------------- bf16 hi/lo split + mma/ldmatrix helpers -------------------
// x = hi + lo, both bf16; products via 3 bf16 MMAs reach ~2^-17 rel precision.
__device__ __forceinline__ void hilo2(float x, float y, uint32_t& h, uint32_t& l)
{
    __nv_bfloat162 hh = __floats2bfloat162_rn(x, y);
    float rx = x - __bfloat162float(hh.x);
    float ry = y - __bfloat162float(hh.y);
    __nv_bfloat162 ll = __floats2bfloat162_rn(rx, ry);
    h = *reinterpret_cast<uint32_t*>(&hh);
    l = *reinterpret_cast<uint32_t*>(&ll);
}

__device__ __forceinline__ void ldsm4(uint32_t* r, const void* p)
{
    uint32_t a = (uint32_t)__cvta_generic_to_shared(p);
    asm volatile("ldmatrix.sync.aligned.m8n8.x4.shared.b16 {%0,%1,%2,%3},[%4];"
        : "=r"(r[0]), "=r"(r[1]), "=r"(r[2]), "=r"(r[3]) : "r"(a));
}
__device__ __forceinline__ void ldsm4t(uint32_t* r, const void* p)
{
    uint32_t a = (uint32_t)__cvta_generic_to_shared(p);
    asm volatile("ldmatrix.sync.aligned.m8n8.x4.trans.shared.b16 {%0,%1,%2,%3},[%4];"
        : "=r"(r[0]), "=r"(r[1]), "=r"(r[2]), "=r"(r[3]) : "r"(a));
}
__device__ __forceinline__ void mma_bf16(float* c, const uint32_t* a,
                                         uint32_t b0, uint32_t b1)
{
    asm volatile(
        "mma.sync.aligned.m16n8k16.row.col.f32.bf16.bf16.f32 "
        "{%0,%1,%2,%3},{%4,%5,%6,%7},{%8,%9},{%0,%1,%2,%3};"
        : "+f"(c[0]), "+f"(c[1]), "+f"(c[2]), "+f"(c[3])
        : "r"(a[0]), "r"(a[1]), "r"(a[2]), "r"(a[3]), "r"(b0), "r"(b1));
}

// ---------------- T5 relative position bias table ---------------------------
__global__ void bias_table_kernel(const float* __restrict__ rel_bias)
{
    int idx = blockIdx.x * blockDim.x + threadIdx.x;
    if (idx >= CH * BIAS_LEN) return;
    int h = idx / BIAS_LEN;
    int t = idx - h * BIAS_LEN;
    int d = t - (CS - 1);

    int base = (d > 0) ? 16 : 0;
    int a = (d < 0) ? -d : d;
    int bucket;
    if (a < 8) {
        bucket = a;
    } else {
        float v = logf((float)a * 0.125f);
        v = v / 2.772588722239781f;     // ln(16)
        v = v * 8.0f;
        int bl = 8 + (int)v;
        bucket = (bl > 15) ? 15 : bl;
    }
    g_bias[h * BIAS_LEN + t] = rel_bias[(base + bucket) * CH + h];
}

// ---------------- projection GEMM: 128x128 tile, bf16x3 mma ------------------
// A[m][k] fp32, W[k][n] fp32, K=N=1024. Smem stores [hi(32) | lo(32)] along k.
#define PLDA 72     // 64 eff-k + 8 pad (bf16); row = 144B, 16B-aligned
#define PLDB 136    // 128 n + 8 pad

__device__ __forceinline__ void mma_gemm_body(
    const float* __restrict__ A, const float* __restrict__ W,
    float* __restrict__ C, int scatter)
{
    __shared__ __nv_bfloat16 Asm[128][PLDA];
    __shared__ __nv_bfloat16 Bsm[64][PLDB];

    const int tid  = threadIdx.x;          // 256 threads = 8 warps
    const int lane = tid & 31;
    const int wid  = tid >> 5;
    const int wm   = wid & 3;              // 4 warps along m (32 rows each)
    const int wn   = wid >> 2;             // 2 warps along n (64 cols each)
    const int g    = lane >> 2;
    const int tq   = lane & 3;

    const float* Ab = A + (size_t)blockIdx.y * 128 * CD;
    const float* Wb = W + blockIdx.x * 128;

    float acc[2][8][4];
    #pragma unroll
    for (int i = 0; i < 2; i++)
        #pragma unroll
        for (int j = 0; j < 8; j++)
            #pragma unroll
            for (int e = 0; e < 4; e++) acc[i][j][e] = 0.f;

    const int ar  = tid >> 1;              // A load: row 0..127
    const int acb = (tid & 1) * 16;        // 16 cols per thread
    const int br  = tid >> 3;              // B load: k-row 0..31
    const int bcb = (tid & 7) * 16;

    for (int k0 = 0; k0 < CD; k0 += 32) {
        __syncthreads();                   // prev-iter mma reads done
        #pragma unroll
        for (int q = 0; q < 4; q++) {
            int c = acb + q * 4;
            float4 f = *(const float4*)(Ab + (size_t)ar * CD + k0 + c);
            uint32_t h0, l0, h1, l1;
            hilo2(f.x, f.y, h0, l0); hilo2(f.z, f.w, h1, l1);
            *(uint32_t*)&Asm[ar][c]      = h0; *(uint32_t*)&Asm[ar][c + 2]      = h1;
            *(uint32_t*)&Asm[ar][32 + c] = l0; *(uint32_t*)&Asm[ar][32 + c + 2] = l1;
        }
        #pragma unroll
        for (int q = 0; q < 4; q++) {
            int c = bcb + q * 4;
            float4 f = *(const float4*)(Wb + (size_t)(k0 + br) * CD + c);
            uint32_t h0, l0, h1, l1;
            hilo2(f.x, f.y, h0, l0); hilo2(f.z, f.w, h1, l1);
            *(uint32_t*)&Bsm[br][c]          = h0; *(uint32_t*)&Bsm[br][c + 2]          = h1;
            *(uint32_t*)&Bsm[32 + br][c]     = l0; *(uint32_t*)&Bsm[32 + br][c + 2]     = l1;
        }
        __syncthreads();

        // 3 pairings x 2 k16-steps: (Ah,Bh),(Ah,Bl),(Al,Bh)
        #pragma unroll
        for (int st = 0; st < 6; st++) {
            const int term = st >> 1, jj = st & 1;
            const int ao = ((term == 2) ? 32 : 0) + jj * 16;
            const int bo = ((term == 1) ? 32 : 0) + jj * 16;
            uint32_t a[2][4];
            #pragma unroll
            for (int mt = 0; mt < 2; mt++)
                ldsm4(a[mt], &Asm[wm * 32 + mt * 16 + (lane & 15)][ao + (lane >> 4) * 8]);
            #pragma unroll
            for (int u = 0; u < 4; u++) {
                uint32_t bb[4];
                ldsm4t(bb, &Bsm[bo + (lane & 15)][wn * 64 + u * 16 + (lane >> 4) * 8]);
                #pragma unroll
                for (int mt = 0; mt < 2; mt++) {
                    mma_bf16(acc[mt][2 * u],     a[mt], bb[0], bb[1]);
                    mma_bf16(acc[mt][2 * u + 1], a[mt], bb[2], bb[3]);
                }
            }
        }
    }

    // epilogue
    #pragma unroll
    for (int mt = 0; mt < 2; mt++) {
        int row = blockIdx.y * 128 + wm * 32 + mt * 16 + g;
        #pragma unroll
        for (int u = 0; u < 8; u++) {
            int col = blockIdx.x * 128 + wn * 64 + u * 8 + 2 * tq;
            float *p0, *p1;
            if (!scatter) {
                p0 = C + (size_t)row * CD + col;
                p1 = p0 + 8 * CD;
            } else {
                int b = row >> 11, s = row & (CS - 1);
                int hh = col >> 6, dk = col & 63;
                p0 = C + ((((size_t)b * CH + hh) * CS + s) * CDK + dk);
                p1 = p0 + 8 * CDK;
            }
            *(float2*)p0 = make_float2(acc[mt][u][0], acc[mt][u][1]);
            *(float2*)p1 = make_float2(acc[mt][u][2], acc[mt][u][3]);
        }
    }
}

__global__ void __launch_bounds__(256) qkv_kernel(
    const float* __restrict__ X,
    const float* __restrict__ Wq, const float* __restrict__ Wk,
    const float* __restrict__ Wv)
{
    const float* W = (blockIdx.z == 0) ? Wq : (blockIdx.z == 1) ? Wk : Wv;
    float* O = (blockIdx.z == 0) ? g_Q : (blockIdx.z == 1) ? g_K : g_V;
    mma_gemm_body(X, W, O, 1);
}

__global__ void __launch_bounds__(256) out_proj_kernel(
    const float* __restrict__ Wo, float* __restrict__ out)
{
    mma_gemm_body(g_AO, Wo, out, 0);
}

// ---------------- fused flash attention, bf16x3 mma -------------------------
#define AQ  128
#define AK  64
#define QLD 136    // 128 eff-d + 8 pad

struct AttnSmem {
    __nv_bfloat16 Qs[AQ][QLD];  // [q][d: hi 0-63 | lo 64-127]
    __nv_bfloat16 Ks[AK][QLD];  // [s][d: hi | lo]
    __nv_bfloat16 Vs[AK][QLD];  // [s][d: hi | lo]
    float bias[CS - 1 + AQ + 1];
};

__global__ void __launch_bounds__(256) attn_kernel()
{
    extern __shared__ char smraw[];
    AttnSmem* sm = reinterpret_cast<AttnSmem*>(smraw);

    const int tid  = threadIdx.x;        // 8 warps; warp w owns q rows 16w..16w+15
    const int lane = tid & 31;
    const int wid  = tid >> 5;
    const int g    = lane >> 2;
    const int tq   = lane & 3;
    const int i0   = blockIdx.x * AQ;
    const int h    = blockIdx.y;
    const int b    = blockIdx.z;

    const size_t hoff = ((size_t)b * CH + h) * CS * CDK;
    const float* Qg = g_Q + hoff + (size_t)i0 * CDK;
    const float* Kg = g_K + hoff;
    const float* Vg = g_V + hoff;

    // Q tile -> smem (hi|lo)
    #pragma unroll
    for (int it = 0; it < 8; it++) {
        int v = tid + it * 256;
        int r = v >> 4, c = (v & 15) * 4;
        float4 f = *(const float4*)(Qg + (size_t)r * CDK + c);
        uint32_t h0, l0, h1, l1;
        hilo2(f.x, f.y, h0, l0); hilo2(f.z, f.w, h1, l1);
        *(uint32_t*)&sm->Qs[r][c]          = h0; *(uint32_t*)&sm->Qs[r][c + 2]          = h1;
        *(uint32_t*)&sm->Qs[r][64 + c]     = l0; *(uint32_t*)&sm->Qs[r][64 + c + 2]     = l1;
    }
    // bias slice
    for (int t = tid; t < CS - 1 + AQ; t += 256)
        sm->bias[t] = g_bias[h * BIAS_LEN + t + CS - i0 - AQ];

    float o[8][4];
    float mrun[2] = {-1e30f, -1e30f}, lrun[2] = {0.f, 0.f};
    #pragma unroll
    for (int u = 0; u < 8; u++)
        #pragma unroll
        for (int e = 0; e < 4; e++) o[u][e] = 0.f;

    const int qlo = wid * 16 + g;   // row of c0/c1 (c2/c3 -> qlo+8)

    for (int kt = 0; kt < CS / AK; kt++) {
        const int kj0 = kt * AK;
        __syncthreads();             // prev-iter mma reads of Ks/Vs done
        #pragma unroll
        for (int it = 0; it < 4; it++) {
            int v = tid + it * 256;
            int r = v >> 4, c = (v & 15) * 4;
            uint32_t h0, l0, h1, l1;
            float4 f = *(const float4*)(Kg + (size_t)(kj0 + r) * CDK + c);
            hilo2(f.x, f.y, h0, l0); hilo2(f.z, f.w, h1, l1);
            *(uint32_t*)&sm->Ks[r][c]      = h0; *(uint32_t*)&sm->Ks[r][c + 2]      = h1;
            *(uint32_t*)&sm->Ks[r][64 + c] = l0; *(uint32_t*)&sm->Ks[r][64 + c + 2] = l1;
            float4 fv = *(const float4*)(Vg + (size_t)(kj0 + r) * CDK + c);
            hilo2(fv.x, fv.y, h0, l0); hilo2(fv.z, fv.w, h1, l1);
            *(uint32_t*)&sm->Vs[r][c]      = h0; *(uint32_t*)&sm->Vs[r][c + 2]      = h1;
            *(uint32_t*)&sm->Vs[r][64 + c] = l0; *(uint32_t*)&sm->Vs[r][64 + c + 2] = l1;
        }
        __syncthreads();

        // ---- S = Q K^T : 3 pairings x 4 k16-steps = 12 ----
        float st[8][4];
        #pragma unroll
        for (int u = 0; u < 8; u++)
            #pragma unroll
            for (int e = 0; e < 4; e++) st[u][e] = 0.f;

        #pragma unroll
        for (int s9 = 0; s9 < 12; s9++) {
            const int term = s9 >> 2, jj = s9 & 3;
            const int ao = ((term == 2) ? 64 : 0) + jj * 16;
            const int bo = ((term == 1) ? 64 : 0) + jj * 16;
            uint32_t a[4];
            ldsm4(a, &sm->Qs[wid * 16 + (lane & 15)][ao + (lane >> 4) * 8]);
            #pragma unroll
            for (int u = 0; u < 4; u++) {
                uint32_t bb[4];   // non-trans on K[s][d]: s=n rows, d=k cols
                ldsm4(bb, &sm->Ks[u * 16 + (lane & 7) + ((lane >> 4) << 3)]
                                 [bo + ((lane >> 3) & 1) * 8]);
                mma_bf16(st[2 * u],     a, bb[0], bb[1]);
                mma_bf16(st[2 * u + 1], a, bb[2], bb[3]);
            }
        }

        // ---- + position bias ----
        #pragma unroll
        for (int u = 0; u < 8; u++) {
            int s0 = kj0 + u * 8 + 2 * tq;
            st[u][0] += sm->bias[s0     - qlo + (AQ - 1)];
            st[u][1] += sm->bias[s0 + 1 - qlo + (AQ - 1)];
            st[u][2] += sm->bias[s0     - qlo - 8 + (AQ - 1)];
            st[u][3] += sm->bias[s0 + 1 - qlo - 8 + (AQ - 1)];
        }

        // ---- online softmax (rows qlo, qlo+8; 4-lane groups share a row) ----
        float ml0 = -1e30f, ml1 = -1e30f;
        #pragma unroll
        for (int u = 0; u < 8; u++) {
            ml0 = fmaxf(ml0, fmaxf(st[u][0], st[u][1]));
            ml1 = fmaxf(ml1, fmaxf(st[u][2], st[u][3]));
        }
        #pragma unroll
        for (int off = 1; off <= 2; off <<= 1) {
            ml0 = fmaxf(ml0, __shfl_xor_sync(0xffffffffu, ml0, off));
            ml1 = fmaxf(ml1, __shfl_xor_sync(0xffffffffu, ml1, off));
        }
        float mn0 = fmaxf(mrun[0], ml0), mn1 = fmaxf(mrun[1], ml1);
        float sc0 = __expf(mrun[0] - mn0), sc1 = __expf(mrun[1] - mn1);
        mrun[0] = mn0; mrun[1] = mn1;
        float ps0 = 0.f, ps1 = 0.f;
        #pragma unroll
        for (int u = 0; u < 8; u++) {
            st[u][0] = __expf(st[u][0] - mn0); ps0 += st[u][0];
            st[u][1] = __expf(st[u][1] - mn0); ps0 += st[u][1];
            st[u][2] = __expf(st[u][2] - mn1); ps1 += st[u][2];
            st[u][3] = __expf(st[u][3] - mn1); ps1 += st[u][3];
        }
        #pragma unroll
        for (int off = 1; off <= 2; off <<= 1) {
            ps0 += __shfl_xor_sync(0xffffffffu, ps0, off);
            ps1 += __shfl_xor_sync(0xffffffffu, ps1, off);
        }
        lrun[0] = lrun[0] * sc0 + ps0;
        lrun[1] = lrun[1] * sc1 + ps1;
        #pragma unroll
        for (int u = 0; u < 8; u++) {
            o[u][0] *= sc0; o[u][1] *= sc0;
            o[u][2] *= sc1; o[u][3] *= sc1;
        }

        // ---- O += P V : P in regs (C-frag -> A-frag), 3 pairings ----
        #pragma unroll
        for (int j = 0; j < 4; j++) {
            uint32_t ah[4], al[4];
            hilo2(st[2*j][0],   st[2*j][1],   ah[0], al[0]); // row g,   k 16j+2t
            hilo2(st[2*j][2],   st[2*j][3],   ah[1], al[1]); // row g+8
            hilo2(st[2*j+1][0], st[2*j+1][1], ah[2], al[2]); // row g,   k+8
            hilo2(st[2*j+1][2], st[2*j+1][3], ah[3], al[3]); // row g+8, k+8
            #pragma unroll
            for (int u = 0; u < 4; u++) {
                uint32_t bh[4], bl[4];
                ldsm4t(bh, &sm->Vs[j * 16 + (lane & 15)][u * 16 + (lane >> 4) * 8]);
                ldsm4t(bl, &sm->Vs[j * 16 + (lane & 15)][64 + u * 16 + (lane >> 4) * 8]);
                mma_bf16(o[2 * u],     ah, bh[0], bh[1]);   // Ph*Vh
                mma_bf16(o[2 * u + 1], ah, bh[2], bh[3]);
                mma_bf16(o[2 * u],     ah, bl[0], bl[1]);   // Ph*Vl
                mma_bf16(o[2 * u + 1], ah, bl[2], bl[3]);
                mma_bf16(o[2 * u],     al, bh[0], bh[1]);   // Pl*Vh
                mma_bf16(o[2 * u + 1], al, bh[2], bh[3]);
            }
        }
    }

    // ---- epilogue: normalize, write [b, s, h*64 + d] ----
    float inv0 = 1.f / lrun[0], inv1 = 1.f / lrun[1];
    int row0 = i0 + qlo;
    #pragma unroll
    for (int u = 0; u < 8; u++) {
        int d = h * CDK + u * 8 + 2 * tq;
        float* p0 = g_AO + ((size_t)b * CS + row0) * CD + d;
        *(float2*)p0            = make_float2(o[u][0] * inv0, o[u][1] * inv0);
        *(float2*)(p0 + 8 * CD) = make_float2(o[u][2] * inv1, o[u][3] * inv1);
    }
}

// ---------------- launch -----------------------------------------------------
extern "C" void kernel_launch(void* const* d_in, const int* in_sizes, int n_in,
                              void* d_out, int out_size)
{
    (void)in_sizes; (void)n_in; (void)out_size;
    const float* X  = (const float*)d_in[0];
    const float* Wq = (const float*)d_in[1];
    const float* Wk = (const float*)d_in[2];
    const float* Wv = (const float*)d_in[3];
    const float* Wo = (const float*)d_in[4];
    const float* rb = (const float*)d_in[5];
    float* out = (float*)d_out;

    // 1) relative-position bias table
    {
        int total = CH * BIAS_LEN;
        bias_table_kernel<<<(total + 255) / 256, 256>>>(rb);
    }
    // 2) fused QKV projections
    {
        dim3 grid(CD / 128, (CB * CS) / 128, 3);
        qkv_kernel<<<grid, 256>>>(X, Wq, Wk, Wv);
    }
    // 3) fused flash attention
    {
        cudaFuncSetAttribute(attn_kernel,
                             cudaFuncAttributeMaxDynamicSharedMemorySize,
                             (int)sizeof(AttnSmem));
        dim3 grid(CS / AQ, CH, CB);
        attn_kernel<<<grid, 256, sizeof(AttnSmem)>>>();
    }
    // 4) output projection -> d_out
    {
        dim3 grid(CD / 128, (CB * CS) / 128);
        out_proj_kernel<<<grid, 256>>>(Wo, out);
    }
}

// round 16
// speedup vs baseline: 3.0953x; 1.0004x over previous
#include <cuda_runtime.h>
#include <cuda_bf16.h>
#include <math.h>
#include <stdint.h>

// Problem constants
#define CB   2
#define CS   2048
#define CD   1024
#define CH   16
#define CDK  64
#define BIAS_LEN (2*CS - 1)   // 4095 relative distances

// ---------------- scratch (static device globals; no runtime allocation) ----
__device__ __align__(16) float g_Q[(size_t)CB*CH*CS*CDK];
__device__ __align__(16) float g_K[(size_t)CB*CH*CS*CDK];
__device__ __align__(16) float g_V[(size_t)CB*CH*CS*CDK];
__device__ __align__(16) float g_AO[(size_t)CB*CS*CD];
__device__ __align__(16) float g_bias[CH*BIAS_LEN];

// ---------------- bf16 hi/lo split + mma/ldmatrix helpers -------------------
// x = hi + lo, both bf16; products via 3 bf16 MMAs reach ~2^-17 rel precision.
__device__ __forceinline__ void hilo2(float x, float y, uint32_t& h, uint32_t& l)
{
    __nv_bfloat162 hh = __floats2bfloat162_rn(x, y);
    float rx = x - __bfloat162float(hh.x);
    float ry = y - __bfloat162float(hh.y);
    __nv_bfloat162 ll = __floats2bfloat162_rn(rx, ry);
    h = *reinterpret_cast<uint32_t*>(&hh);
    l = *reinterpret_cast<uint32_t*>(&ll);
}

__device__ __forceinline__ void ldsm4(uint32_t* r, const void* p)
{
    uint32_t a = (uint32_t)__cvta_generic_to_shared(p);
    asm volatile("ldmatrix.sync.aligned.m8n8.x4.shared.b16 {%0,%1,%2,%3},[%4];"
        : "=r"(r[0]), "=r"(r[1]), "=r"(r[2]), "=r"(r[3]) : "r"(a));
}
__device__ __forceinline__ void ldsm4t(uint32_t* r, const void* p)
{
    uint32_t a = (uint32_t)__cvta_generic_to_shared(p);
    asm volatile("ldmatrix.sync.aligned.m8n8.x4.trans.shared.b16 {%0,%1,%2,%3},[%4];"
        : "=r"(r[0]), "=r"(r[1]), "=r"(r[2]), "=r"(r[3]) : "r"(a));
}
__device__ __forceinline__ void mma_bf16(float* c, const uint32_t* a,
                                         uint32_t b0, uint32_t b1)
{
    asm volatile(
        "mma.sync.aligned.m16n8k16.row.col.f32.bf16.bf16.f32 "
        "{%0,%1,%2,%3},{%4,%5,%6,%7},{%8,%9},{%0,%1,%2,%3};"
        : "+f"(c[0]), "+f"(c[1]), "+f"(c[2]), "+f"(c[3])
        : "r"(a[0]), "r"(a[1]), "r"(a[2]), "r"(a[3]), "r"(b0), "r"(b1));
}

// ---------------- T5 relative position bias table ---------------------------
__global__ void bias_table_kernel(const float* __restrict__ rel_bias)
{
    int idx = blockIdx.x * blockDim.x + threadIdx.x;
    if (idx >= CH * BIAS_LEN) return;
    int h = idx / BIAS_LEN;
    int t = idx - h * BIAS_LEN;
    int d = t - (CS - 1);

    int base = (d > 0) ? 16 : 0;
    int a = (d < 0) ? -d : d;
    int bucket;
    if (a < 8) {
        bucket = a;
    } else {
        float v = logf((float)a * 0.125f);
        v = v / 2.772588722239781f;     // ln(16)
        v = v * 8.0f;
        int bl = 8 + (int)v;
        bucket = (bl > 15) ? 15 : bl;
    }
    g_bias[h * BIAS_LEN + t] = rel_bias[(base + bucket) * CH + h];
}

// ---------------- projection GEMM: 128x128 tile, bf16x3 mma ------------------
// A[m][k] fp32, W[k][n] fp32, K=N=1024. Smem stores [hi(32) | lo(32)] along k.
#define PLDA 72     // 64 eff-k + 8 pad (bf16); row = 144B, 16B-aligned
#define PLDB 136    // 128 n + 8 pad

__device__ __forceinline__ void mma_gemm_body(
    const float* __restrict__ A, const float* __restrict__ W,
    float* __restrict__ C, int scatter)
{
    __shared__ __nv_bfloat16 Asm[128][PLDA];
    __shared__ __nv_bfloat16 Bsm[64][PLDB];

    const int tid  = threadIdx.x;          // 256 threads = 8 warps
    const int lane = tid & 31;
    const int wid  = tid >> 5;
    const int wm   = wid & 3;              // 4 warps along m (32 rows each)
    const int wn   = wid >> 2;             // 2 warps along n (64 cols each)
    const int g    = lane >> 2;
    const int tq   = lane & 3;

    const float* Ab = A + (size_t)blockIdx.y * 128 * CD;
    const float* Wb = W + blockIdx.x * 128;

    float acc[2][8][4];
    #pragma unroll
    for (int i = 0; i < 2; i++)
        #pragma unroll
        for (int j = 0; j < 8; j++)
            #pragma unroll
            for (int e = 0; e < 4; e++) acc[i][j][e] = 0.f;

    const int ar  = tid >> 1;              // A load: row 0..127
    const int acb = (tid & 1) * 16;        // 16 cols per thread
    const int br  = tid >> 3;              // B load: k-row 0..31
    const int bcb = (tid & 7) * 16;

    for (int k0 = 0; k0 < CD; k0 += 32) {
        __syncthreads();                   // prev-iter mma reads done
        #pragma unroll
        for (int q = 0; q < 4; q++) {
            int c = acb + q * 4;
            float4 f = *(const float4*)(Ab + (size_t)ar * CD + k0 + c);
            uint32_t h0, l0, h1, l1;
            hilo2(f.x, f.y, h0, l0); hilo2(f.z, f.w, h1, l1);
            *(uint32_t*)&Asm[ar][c]      = h0; *(uint32_t*)&Asm[ar][c + 2]      = h1;
            *(uint32_t*)&Asm[ar][32 + c] = l0; *(uint32_t*)&Asm[ar][32 + c + 2] = l1;
        }
        #pragma unroll
        for (int q = 0; q < 4; q++) {
            int c = bcb + q * 4;
            float4 f = *(const float4*)(Wb + (size_t)(k0 + br) * CD + c);
            uint32_t h0, l0, h1, l1;
            hilo2(f.x, f.y, h0, l0); hilo2(f.z, f.w, h1, l1);
            *(uint32_t*)&Bsm[br][c]          = h0; *(uint32_t*)&Bsm[br][c + 2]          = h1;
            *(uint32_t*)&Bsm[32 + br][c]     = l0; *(uint32_t*)&Bsm[32 + br][c + 2]     = l1;
        }
        __syncthreads();

        // 3 pairings x 2 k16-steps: (Ah,Bh),(Ah,Bl),(Al,Bh)
        #pragma unroll
        for (int st = 0; st < 6; st++) {
            const int term = st >> 1, jj = st & 1;
            const int ao = ((term == 2) ? 32 : 0) + jj * 16;
            const int bo = ((term == 1) ? 32 : 0) + jj * 16;
            uint32_t a[2][4];
            #pragma unroll
            for (int mt = 0; mt < 2; mt++)
                ldsm4(a[mt], &Asm[wm * 32 + mt * 16 + (lane & 15)][ao + (lane >> 4) * 8]);
            #pragma unroll
            for (int u = 0; u < 4; u++) {
                uint32_t bb[4];
                ldsm4t(bb, &Bsm[bo + (lane & 15)][wn * 64 + u * 16 + (lane >> 4) * 8]);
                #pragma unroll
                for (int mt = 0; mt < 2; mt++) {
                    mma_bf16(acc[mt][2 * u],     a[mt], bb[0], bb[1]);
                    mma_bf16(acc[mt][2 * u + 1], a[mt], bb[2], bb[3]);
                }
            }
        }
    }

    // epilogue
    #pragma unroll
    for (int mt = 0; mt < 2; mt++) {
        int row = blockIdx.y * 128 + wm * 32 + mt * 16 + g;
        #pragma unroll
        for (int u = 0; u < 8; u++) {
            int col = blockIdx.x * 128 + wn * 64 + u * 8 + 2 * tq;
            float *p0, *p1;
            if (!scatter) {
                p0 = C + (size_t)row * CD + col;
                p1 = p0 + 8 * CD;
            } else {
                int b = row >> 11, s = row & (CS - 1);
                int hh = col >> 6, dk = col & 63;
                p0 = C + ((((size_t)b * CH + hh) * CS + s) * CDK + dk);
                p1 = p0 + 8 * CDK;
            }
            *(float2*)p0 = make_float2(acc[mt][u][0], acc[mt][u][1]);
            *(float2*)p1 = make_float2(acc[mt][u][2], acc[mt][u][3]);
        }
    }
}

__global__ void __launch_bounds__(256) qkv_kernel(
    const float* __restrict__ X,
    const float* __restrict__ Wq, const float* __restrict__ Wk,
    const float* __restrict__ Wv)
{
    const float* W = (blockIdx.z == 0) ? Wq : (blockIdx.z == 1) ? Wk : Wv;
    float* O = (blockIdx.z == 0) ? g_Q : (blockIdx.z == 1) ? g_K : g_V;
    mma_gemm_body(X, W, O, 1);
}

__global__ void __launch_bounds__(256) out_proj_kernel(
    const float* __restrict__ Wo, float* __restrict__ out)
{
    mma_gemm_body(g_AO, Wo, out, 0);
}

// ---------------- fused flash attention, bf16x3 mma -------------------------
#define AQ  128
#define AK  64
#define QLD 136    // 128 eff-d + 8 pad

struct AttnSmem {
    __nv_bfloat16 Qs[AQ][QLD];  // [q][d: hi 0-63 | lo 64-127]
    __nv_bfloat16 Ks[AK][QLD];  // [s][d: hi | lo]
    __nv_bfloat16 Vs[AK][QLD];  // [s][d: hi | lo]
    float bias[CS - 1 + AQ + 1];
};

__global__ void __launch_bounds__(256) attn_kernel()
{
    extern __shared__ char smraw[];
    AttnSmem* sm = reinterpret_cast<AttnSmem*>(smraw);

    const int tid  = threadIdx.x;        // 8 warps; warp w owns q rows 16w..16w+15
    const int lane = tid & 31;
    const int wid  = tid >> 5;
    const int g    = lane >> 2;
    const int tq   = lane & 3;
    const int i0   = blockIdx.x * AQ;
    const int h    = blockIdx.y;
    const int b    = blockIdx.z;

    const size_t hoff = ((size_t)b * CH + h) * CS * CDK;
    const float* Qg = g_Q + hoff + (size_t)i0 * CDK;
    const float* Kg = g_K + hoff;
    const float* Vg = g_V + hoff;

    // Q tile -> smem (hi|lo)
    #pragma unroll
    for (int it = 0; it < 8; it++) {
        int v = tid + it * 256;
        int r = v >> 4, c = (v & 15) * 4;
        float4 f = *(const float4*)(Qg + (size_t)r * CDK + c);
        uint32_t h0, l0, h1, l1;
        hilo2(f.x, f.y, h0, l0); hilo2(f.z, f.w, h1, l1);
        *(uint32_t*)&sm->Qs[r][c]          = h0; *(uint32_t*)&sm->Qs[r][c + 2]          = h1;
        *(uint32_t*)&sm->Qs[r][64 + c]     = l0; *(uint32_t*)&sm->Qs[r][64 + c + 2]     = l1;
    }
    // bias slice
    for (int t = tid; t < CS - 1 + AQ; t += 256)
        sm->bias[t] = g_bias[h * BIAS_LEN + t + CS - i0 - AQ];

    float o[8][4];
    float mrun[2] = {-1e30f, -1e30f}, lrun[2] = {0.f, 0.f};
    #pragma unroll
    for (int u = 0; u < 8; u++)
        #pragma unroll
        for (int e = 0; e < 4; e++) o[u][e] = 0.f;

    const int qlo = wid * 16 + g;   // row of c0/c1 (c2/c3 -> qlo+8)

    for (int kt = 0; kt < CS / AK; kt++) {
        const int kj0 = kt * AK;
        __syncthreads();             // prev-iter mma reads of Ks/Vs done
        #pragma unroll
        for (int it = 0; it < 4; it++) {
            int v = tid + it * 256;
            int r = v >> 4, c = (v & 15) * 4;
            uint32_t h0, l0, h1, l1;
            float4 f = *(const float4*)(Kg + (size_t)(kj0 + r) * CDK + c);
            hilo2(f.x, f.y, h0, l0); hilo2(f.z, f.w, h1, l1);
            *(uint32_t*)&sm->Ks[r][c]      = h0; *(uint32_t*)&sm->Ks[r][c + 2]      = h1;
            *(uint32_t*)&sm->Ks[r][64 + c] = l0; *(uint32_t*)&sm->Ks[r][64 + c + 2] = l1;
            float4 fv = *(const float4*)(Vg + (size_t)(kj0 + r) * CDK + c);
            hilo2(fv.x, fv.y, h0, l0); hilo2(fv.z, fv.w, h1, l1);
            *(uint32_t*)&sm->Vs[r][c]      = h0; *(uint32_t*)&sm->Vs[r][c + 2]      = h1;
            *(uint32_t*)&sm->Vs[r][64 + c] = l0; *(uint32_t*)&sm->Vs[r][64 + c + 2] = l1;
        }
        __syncthreads();

        // ---- S = Q K^T : 3 pairings x 4 k16-steps = 12 ----
        float st[8][4];
        #pragma unroll
        for (int u = 0; u < 8; u++)
            #pragma unroll
            for (int e = 0; e < 4; e++) st[u][e] = 0.f;

        #pragma unroll
        for (int s9 = 0; s9 < 12; s9++) {
            const int term = s9 >> 2, jj = s9 & 3;
            const int ao = ((term == 2) ? 64 : 0) + jj * 16;
            const int bo = ((term == 1) ? 64 : 0) + jj * 16;
            uint32_t a[4];
            ldsm4(a, &sm->Qs[wid * 16 + (lane & 15)][ao + (lane >> 4) * 8]);
            #pragma unroll
            for (int u = 0; u < 4; u++) {
                uint32_t bb[4];   // non-trans on K[s][d]: s=n rows, d=k cols
                ldsm4(bb, &sm->Ks[u * 16 + (lane & 7) + ((lane >> 4) << 3)]
                                 [bo + ((lane >> 3) & 1) * 8]);
                mma_bf16(st[2 * u],     a, bb[0], bb[1]);
                mma_bf16(st[2 * u + 1], a, bb[2], bb[3]);
            }
        }

        // ---- + position bias ----
        #pragma unroll
        for (int u = 0; u < 8; u++) {
            int s0 = kj0 + u * 8 + 2 * tq;
            st[u][0] += sm->bias[s0     - qlo + (AQ - 1)];
            st[u][1] += sm->bias[s0 + 1 - qlo + (AQ - 1)];
            st[u][2] += sm->bias[s0     - qlo - 8 + (AQ - 1)];
            st[u][3] += sm->bias[s0 + 1 - qlo - 8 + (AQ - 1)];
        }

        // ---- online softmax (rows qlo, qlo+8; 4-lane groups share a row) ----
        float ml0 = -1e30f, ml1 = -1e30f;
        #pragma unroll
        for (int u = 0; u < 8; u++) {
            ml0 = fmaxf(ml0, fmaxf(st[u][0], st[u][1]));
            ml1 = fmaxf(ml1, fmaxf(st[u][2], st[u][3]));
        }
        #pragma unroll
        for (int off = 1; off <= 2; off <<= 1) {
            ml0 = fmaxf(ml0, __shfl_xor_sync(0xffffffffu, ml0, off));
            ml1 = fmaxf(ml1, __shfl_xor_sync(0xffffffffu, ml1, off));
        }
        float mn0 = fmaxf(mrun[0], ml0), mn1 = fmaxf(mrun[1], ml1);
        float sc0 = __expf(mrun[0] - mn0), sc1 = __expf(mrun[1] - mn1);
        mrun[0] = mn0; mrun[1] = mn1;
        float ps0 = 0.f, ps1 = 0.f;
        #pragma unroll
        for (int u = 0; u < 8; u++) {
            st[u][0] = __expf(st[u][0] - mn0); ps0 += st[u][0];
            st[u][1] = __expf(st[u][1] - mn0); ps0 += st[u][1];
            st[u][2] = __expf(st[u][2] - mn1); ps1 += st[u][2];
            st[u][3] = __expf(st[u][3] - mn1); ps1 += st[u][3];
        }
        #pragma unroll
        for (int off = 1; off <= 2; off <<= 1) {
            ps0 += __shfl_xor_sync(0xffffffffu, ps0, off);
            ps1 += __shfl_xor_sync(0xffffffffu, ps1, off);
        }
        lrun[0] = lrun[0] * sc0 + ps0;
        lrun[1] = lrun[1] * sc1 + ps1;
        #pragma unroll
        for (int u = 0; u < 8; u++) {
            o[u][0] *= sc0; o[u][1] *= sc0;
            o[u][2] *= sc1; o[u][3] *= sc1;
        }

        // ---- O += P V : P in regs (C-frag -> A-frag), 3 pairings ----
        #pragma unroll
        for (int j = 0; j < 4; j++) {
            uint32_t ah[4], al[4];
            hilo2(st[2*j][0],   st[2*j][1],   ah[0], al[0]); // row g,   k 16j+2t
            hilo2(st[2*j][2],   st[2*j][3],   ah[1], al[1]); // row g+8
            hilo2(st[2*j+1][0], st[2*j+1][1], ah[2], al[2]); // row g,   k+8
            hilo2(st[2*j+1][2], st[2*j+1][3], ah[3], al[3]); // row g+8, k+8
            #pragma unroll
            for (int u = 0; u < 4; u++) {
                uint32_t bh[4], bl[4];
                ldsm4t(bh, &sm->Vs[j * 16 + (lane & 15)][u * 16 + (lane >> 4) * 8]);
                ldsm4t(bl, &sm->Vs[j * 16 + (lane & 15)][64 + u * 16 + (lane >> 4) * 8]);
                mma_bf16(o[2 * u],     ah, bh[0], bh[1]);   // Ph*Vh
                mma_bf16(o[2 * u + 1], ah, bh[2], bh[3]);
                mma_bf16(o[2 * u],     ah, bl[0], bl[1]);   // Ph*Vl
                mma_bf16(o[2 * u + 1], ah, bl[2], bl[3]);
                mma_bf16(o[2 * u],     al, bh[0], bh[1]);   // Pl*Vh
                mma_bf16(o[2 * u + 1], al, bh[2], bh[3]);
            }
        }
    }

    // ---- epilogue: normalize, write [b, s, h*64 + d] ----
    float inv0 = 1.f / lrun[0], inv1 = 1.f / lrun[1];
    int row0 = i0 + qlo;
    #pragma unroll
    for (int u = 0; u < 8; u++) {
        int d = h * CDK + u * 8 + 2 * tq;
        float* p0 = g_AO + ((size_t)b * CS + row0) * CD + d;
        *(float2*)p0            = make_float2(o[u][0] * inv0, o[u][1] * inv0);
        *(float2*)(p0 + 8 * CD) = make_float2(o[u][2] * inv1, o[u][3] * inv1);
    }
}

// ---------------- launch -----------------------------------------------------
extern "C" void kernel_launch(void* const* d_in, const int* in_sizes, int n_in,
                              void* d_out, int out_size)
{
    (void)in_sizes; (void)n_in; (void)out_size;
    const float* X  = (const float*)d_in[0];
    const float* Wq = (const float*)d_in[1];
    const float* Wk = (const float*)d_in[2];
    const float* Wv = (const float*)d_in[3];
    const float* Wo = (const float*)d_in[4];
    const float* rb = (const float*)d_in[5];
    float* out = (float*)d_out;

    // 1) relative-position bias table
    {
        int total = CH * BIAS_LEN;
        bias_table_kernel<<<(total + 255) / 256, 256>>>(rb);
    }
    // 2) fused QKV projections
    {
        dim3 grid(CD / 128, (CB * CS) / 128, 3);
        qkv_kernel<<<grid, 256>>>(X, Wq, Wk, Wv);
    }
    // 3) fused flash attention
    {
        cudaFuncSetAttribute(attn_kernel,
                             cudaFuncAttributeMaxDynamicSharedMemorySize,
                             (int)sizeof(AttnSmem));
        dim3 grid(CS / AQ, CH, CB);
        attn_kernel<<<grid, 256, sizeof(AttnSmem)>>>();
    }
    // 4) output projection -> d_out
    {
        dim3 grid(CD / 128, (CB * CS) / 128);
        out_proj_kernel<<<grid, 256>>>(Wo, out);
    }
}

// round 17
// speedup vs baseline: 3.4021x; 1.0991x over previous
#include <cuda_runtime.h>
#include <cuda_bf16.h>
#include <math.h>
#include <stdint.h>

// Problem constants
#define CB   2
#define CS   2048
#define CD   1024
#define CH   16
#define CDK  64
#define BIAS_LEN (2*CS - 1)   // 4095 relative distances

// ---------------- scratch (static device globals; no runtime allocation) ----
__device__ __align__(16) float g_Q[(size_t)CB*CH*CS*CDK];
__device__ __align__(16) float g_K[(size_t)CB*CH*CS*CDK];
__device__ __align__(16) float g_V[(size_t)CB*CH*CS*CDK];
__device__ __align__(16) float g_AO[(size_t)CB*CS*CD];
__device__ __align__(16) float g_bias[CH*BIAS_LEN];

// ---------------- bf16 hi/lo split + mma/ldmatrix helpers -------------------
__device__ __forceinline__ void hilo2(float x, float y, uint32_t& h, uint32_t& l)
{
    __nv_bfloat162 hh = __floats2bfloat162_rn(x, y);
    float rx = x - __bfloat162float(hh.x);
    float ry = y - __bfloat162float(hh.y);
    __nv_bfloat162 ll = __floats2bfloat162_rn(rx, ry);
    h = *reinterpret_cast<uint32_t*>(&hh);
    l = *reinterpret_cast<uint32_t*>(&ll);
}

__device__ __forceinline__ void ldsm4(uint32_t* r, const void* p)
{
    uint32_t a = (uint32_t)__cvta_generic_to_shared(p);
    asm volatile("ldmatrix.sync.aligned.m8n8.x4.shared.b16 {%0,%1,%2,%3},[%4];"
        : "=r"(r[0]), "=r"(r[1]), "=r"(r[2]), "=r"(r[3]) : "r"(a));
}
__device__ __forceinline__ void ldsm4t(uint32_t* r, const void* p)
{
    uint32_t a = (uint32_t)__cvta_generic_to_shared(p);
    asm volatile("ldmatrix.sync.aligned.m8n8.x4.trans.shared.b16 {%0,%1,%2,%3},[%4];"
        : "=r"(r[0]), "=r"(r[1]), "=r"(r[2]), "=r"(r[3]) : "r"(a));
}
__device__ __forceinline__ void mma_bf16(float* c, const uint32_t* a,
                                         uint32_t b0, uint32_t b1)
{
    asm volatile(
        "mma.sync.aligned.m16n8k16.row.col.f32.bf16.bf16.f32 "
        "{%0,%1,%2,%3},{%4,%5,%6,%7},{%8,%9},{%0,%1,%2,%3};"
        : "+f"(c[0]), "+f"(c[1]), "+f"(c[2]), "+f"(c[3])
        : "r"(a[0]), "r"(a[1]), "r"(a[2]), "r"(a[3]), "r"(b0), "r"(b1));
}

// ---------------- T5 relative position bias table ---------------------------
__global__ void bias_table_kernel(const float* __restrict__ rel_bias)
{
    int idx = blockIdx.x * blockDim.x + threadIdx.x;
    if (idx >= CH * BIAS_LEN) return;
    int h = idx / BIAS_LEN;
    int t = idx - h * BIAS_LEN;
    int d = t - (CS - 1);

    int base = (d > 0) ? 16 : 0;
    int a = (d < 0) ? -d : d;
    int bucket;
    if (a < 8) {
        bucket = a;
    } else {
        float v = logf((float)a * 0.125f);
        v = v / 2.772588722239781f;     // ln(16)
        v = v * 8.0f;
        int bl = 8 + (int)v;
        bucket = (bl > 15) ? 15 : bl;
    }
    g_bias[h * BIAS_LEN + t] = rel_bias[(base + bucket) * CH + h];
}

// ---------------- projection GEMM: 128x128 tile, bf16x3 mma ------------------
// A[m][k] fp32, W[k][n] fp32, K=N=1024. Smem stores [hi(32) | lo(32)] along k.
#define PLDA 72     // 64 eff-k + 8 pad (bf16)
#define PLDB 136    // 128 n + 8 pad

__device__ __forceinline__ void mma_gemm_body(
    const float* __restrict__ A, const float* __restrict__ W,
    float* __restrict__ C, int scatter)
{
    __shared__ __nv_bfloat16 Asm[128][PLDA];
    __shared__ __nv_bfloat16 Bsm[64][PLDB];

    const int tid  = threadIdx.x;          // 256 threads = 8 warps
    const int lane = tid & 31;
    const int wid  = tid >> 5;
    const int wm   = wid & 3;              // 4 warps along m (32 rows each)
    const int wn   = wid >> 2;             // 2 warps along n (64 cols each)
    const int g    = lane >> 2;
    const int tq   = lane & 3;

    const float* Ab = A + (size_t)blockIdx.y * 128 * CD;
    const float* Wb = W + blockIdx.x * 128;

    float acc[2][8][4];
    #pragma unroll
    for (int i = 0; i < 2; i++)
        #pragma unroll
        for (int j = 0; j < 8; j++)
            #pragma unroll
            for (int e = 0; e < 4; e++) acc[i][j][e] = 0.f;

    const int ar  = tid >> 1;              // A load: row 0..127
    const int acb = (tid & 1) * 16;        // 16 cols per thread
    const int br  = tid >> 3;              // B load: k-row 0..31
    const int bcb = (tid & 7) * 16;

    for (int k0 = 0; k0 < CD; k0 += 32) {
        __syncthreads();                   // prev-iter mma reads done
        #pragma unroll
        for (int q = 0; q < 4; q++) {
            int c = acb + q * 4;
            float4 f = *(const float4*)(Ab + (size_t)ar * CD + k0 + c);
            uint32_t h0, l0, h1, l1;
            hilo2(f.x, f.y, h0, l0); hilo2(f.z, f.w, h1, l1);
            *(uint32_t*)&Asm[ar][c]      = h0; *(uint32_t*)&Asm[ar][c + 2]      = h1;
            *(uint32_t*)&Asm[ar][32 + c] = l0; *(uint32_t*)&Asm[ar][32 + c + 2] = l1;
        }
        #pragma unroll
        for (int q = 0; q < 4; q++) {
            int c = bcb + q * 4;
            float4 f = *(const float4*)(Wb + (size_t)(k0 + br) * CD + c);
            uint32_t h0, l0, h1, l1;
            hilo2(f.x, f.y, h0, l0); hilo2(f.z, f.w, h1, l1);
            *(uint32_t*)&Bsm[br][c]      = h0; *(uint32_t*)&Bsm[br][c + 2]      = h1;
            *(uint32_t*)&Bsm[32 + br][c] = l0; *(uint32_t*)&Bsm[32 + br][c + 2] = l1;
        }
        __syncthreads();

        // frag-cached: load Ah/Al once per jj, Bh/Bl once per u; 3 pairings
        // (Ah*Bh, Ah*Bl, Al*Bh) fired from registers.
        #pragma unroll
        for (int jj = 0; jj < 2; jj++) {
            uint32_t ah[2][4], al[2][4];
            #pragma unroll
            for (int mt = 0; mt < 2; mt++) {
                const __nv_bfloat16* arow = &Asm[wm * 32 + mt * 16 + (lane & 15)][0];
                ldsm4(ah[mt], arow + jj * 16 + (lane >> 4) * 8);
                ldsm4(al[mt], arow + 32 + jj * 16 + (lane >> 4) * 8);
            }
            #pragma unroll
            for (int u = 0; u < 4; u++) {
                uint32_t bh[4], bl[4];
                ldsm4t(bh, &Bsm[jj * 16 + (lane & 15)]
                               [wn * 64 + u * 16 + (lane >> 4) * 8]);
                ldsm4t(bl, &Bsm[32 + jj * 16 + (lane & 15)]
                               [wn * 64 + u * 16 + (lane >> 4) * 8]);
                #pragma unroll
                for (int mt = 0; mt < 2; mt++) {
                    mma_bf16(acc[mt][2 * u],     ah[mt], bh[0], bh[1]);
                    mma_bf16(acc[mt][2 * u + 1], ah[mt], bh[2], bh[3]);
                    mma_bf16(acc[mt][2 * u],     ah[mt], bl[0], bl[1]);
                    mma_bf16(acc[mt][2 * u + 1], ah[mt], bl[2], bl[3]);
                    mma_bf16(acc[mt][2 * u],     al[mt], bh[0], bh[1]);
                    mma_bf16(acc[mt][2 * u + 1], al[mt], bh[2], bh[3]);
                }
            }
        }
    }

    // epilogue
    #pragma unroll
    for (int mt = 0; mt < 2; mt++) {
        int row = blockIdx.y * 128 + wm * 32 + mt * 16 + g;
        #pragma unroll
        for (int u = 0; u < 8; u++) {
            int col = blockIdx.x * 128 + wn * 64 + u * 8 + 2 * tq;
            float *p0, *p1;
            if (!scatter) {
                p0 = C + (size_t)row * CD + col;
                p1 = p0 + 8 * CD;
            } else {
                int b = row >> 11, s = row & (CS - 1);
                int hh = col >> 6, dk = col & 63;
                p0 = C + ((((size_t)b * CH + hh) * CS + s) * CDK + dk);
                p1 = p0 + 8 * CDK;
            }
            *(float2*)p0 = make_float2(acc[mt][u][0], acc[mt][u][1]);
            *(float2*)p1 = make_float2(acc[mt][u][2], acc[mt][u][3]);
        }
    }
}

__global__ void __launch_bounds__(256) qkv_kernel(
    const float* __restrict__ X,
    const float* __restrict__ Wq, const float* __restrict__ Wk,
    const float* __restrict__ Wv)
{
    const float* W = (blockIdx.z == 0) ? Wq : (blockIdx.z == 1) ? Wk : Wv;
    float* O = (blockIdx.z == 0) ? g_Q : (blockIdx.z == 1) ? g_K : g_V;
    mma_gemm_body(X, W, O, 1);
}

__global__ void __launch_bounds__(256) out_proj_kernel(
    const float* __restrict__ Wo, float* __restrict__ out)
{
    mma_gemm_body(g_AO, Wo, out, 0);
}

// ---------------- fused flash attention, bf16x3 mma -------------------------
#define AQ  128
#define AK  64
#define QLD 136    // 128 eff-d + 8 pad

struct AttnSmem {
    __nv_bfloat16 Qs[AQ][QLD];  // [q][d: hi 0-63 | lo 64-127]
    __nv_bfloat16 Ks[AK][QLD];  // [s][d: hi | lo]
    __nv_bfloat16 Vs[AK][QLD];  // [s][d: hi | lo]
    float bias[CS - 1 + AQ + 1];
};

__global__ void __launch_bounds__(256) attn_kernel()
{
    extern __shared__ char smraw[];
    AttnSmem* sm = reinterpret_cast<AttnSmem*>(smraw);

    const int tid  = threadIdx.x;        // 8 warps; warp w owns q rows 16w..16w+15
    const int lane = tid & 31;
    const int wid  = tid >> 5;
    const int g    = lane >> 2;
    const int tq   = lane & 3;
    const int i0   = blockIdx.x * AQ;
    const int h    = blockIdx.y;
    const int b    = blockIdx.z;

    const size_t hoff = ((size_t)b * CH + h) * CS * CDK;
    const float* Qg = g_Q + hoff + (size_t)i0 * CDK;
    const float* Kg = g_K + hoff;
    const float* Vg = g_V + hoff;

    // Q tile -> smem (hi|lo)
    #pragma unroll
    for (int it = 0; it < 8; it++) {
        int v = tid + it * 256;
        int r = v >> 4, c = (v & 15) * 4;
        float4 f = *(const float4*)(Qg + (size_t)r * CDK + c);
        uint32_t h0, l0, h1, l1;
        hilo2(f.x, f.y, h0, l0); hilo2(f.z, f.w, h1, l1);
        *(uint32_t*)&sm->Qs[r][c]      = h0; *(uint32_t*)&sm->Qs[r][c + 2]      = h1;
        *(uint32_t*)&sm->Qs[r][64 + c] = l0; *(uint32_t*)&sm->Qs[r][64 + c + 2] = l1;
    }
    // bias slice
    for (int t = tid; t < CS - 1 + AQ; t += 256)
        sm->bias[t] = g_bias[h * BIAS_LEN + t + CS - i0 - AQ];

    float o[8][4];
    float mrun[2] = {-1e30f, -1e30f}, lrun[2] = {0.f, 0.f};
    #pragma unroll
    for (int u = 0; u < 8; u++)
        #pragma unroll
        for (int e = 0; e < 4; e++) o[u][e] = 0.f;

    const int qlo = wid * 16 + g;   // row of c0/c1 (c2/c3 -> qlo+8)

    for (int kt = 0; kt < CS / AK; kt++) {
        const int kj0 = kt * AK;
        __syncthreads();             // prev-iter mma reads of Ks/Vs done
        #pragma unroll
        for (int it = 0; it < 4; it++) {
            int v = tid + it * 256;
            int r = v >> 4, c = (v & 15) * 4;
            uint32_t h0, l0, h1, l1;
            float4 f = *(const float4*)(Kg + (size_t)(kj0 + r) * CDK + c);
            hilo2(f.x, f.y, h0, l0); hilo2(f.z, f.w, h1, l1);
            *(uint32_t*)&sm->Ks[r][c]      = h0; *(uint32_t*)&sm->Ks[r][c + 2]      = h1;
            *(uint32_t*)&sm->Ks[r][64 + c] = l0; *(uint32_t*)&sm->Ks[r][64 + c + 2] = l1;
            float4 fv = *(const float4*)(Vg + (size_t)(kj0 + r) * CDK + c);
            hilo2(fv.x, fv.y, h0, l0); hilo2(fv.z, fv.w, h1, l1);
            *(uint32_t*)&sm->Vs[r][c]      = h0; *(uint32_t*)&sm->Vs[r][c + 2]      = h1;
            *(uint32_t*)&sm->Vs[r][64 + c] = l0; *(uint32_t*)&sm->Vs[r][64 + c + 2] = l1;
        }
        __syncthreads();

        // ---- S = Q K^T : frag-cached 3 pairings over 4 k16-steps ----
        float st[8][4];
        #pragma unroll
        for (int u = 0; u < 8; u++)
            #pragma unroll
            for (int e = 0; e < 4; e++) st[u][e] = 0.f;

        #pragma unroll
        for (int jj = 0; jj < 4; jj++) {
            uint32_t qh[4], ql[4];
            const __nv_bfloat16* qrow = &sm->Qs[wid * 16 + (lane & 15)][0];
            ldsm4(qh, qrow + jj * 16 + (lane >> 4) * 8);
            ldsm4(ql, qrow + 64 + jj * 16 + (lane >> 4) * 8);
            #pragma unroll
            for (int u = 0; u < 4; u++) {
                uint32_t kh[4], kl[4];
                const __nv_bfloat16* krow =
                    &sm->Ks[u * 16 + (lane & 7) + ((lane >> 4) << 3)][0];
                ldsm4(kh, krow + jj * 16 + ((lane >> 3) & 1) * 8);
                ldsm4(kl, krow + 64 + jj * 16 + ((lane >> 3) & 1) * 8);
                mma_bf16(st[2 * u],     qh, kh[0], kh[1]);
                mma_bf16(st[2 * u + 1], qh, kh[2], kh[3]);
                mma_bf16(st[2 * u],     qh, kl[0], kl[1]);
                mma_bf16(st[2 * u + 1], qh, kl[2], kl[3]);
                mma_bf16(st[2 * u],     ql, kh[0], kh[1]);
                mma_bf16(st[2 * u + 1], ql, kh[2], kh[3]);
            }
        }

        // ---- + position bias ----
        #pragma unroll
        for (int u = 0; u < 8; u++) {
            int s0 = kj0 + u * 8 + 2 * tq;
            st[u][0] += sm->bias[s0     - qlo + (AQ - 1)];
            st[u][1] += sm->bias[s0 + 1 - qlo + (AQ - 1)];
            st[u][2] += sm->bias[s0     - qlo - 8 + (AQ - 1)];
            st[u][3] += sm->bias[s0 + 1 - qlo - 8 + (AQ - 1)];
        }

        // ---- online softmax (rows qlo, qlo+8; 4-lane groups share a row) ----
        float ml0 = -1e30f, ml1 = -1e30f;
        #pragma unroll
        for (int u = 0; u < 8; u++) {
            ml0 = fmaxf(ml0, fmaxf(st[u][0], st[u][1]));
            ml1 = fmaxf(ml1, fmaxf(st[u][2], st[u][3]));
        }
        #pragma unroll
        for (int off = 1; off <= 2; off <<= 1) {
            ml0 = fmaxf(ml0, __shfl_xor_sync(0xffffffffu, ml0, off));
            ml1 = fmaxf(ml1, __shfl_xor_sync(0xffffffffu, ml1, off));
        }
        float mn0 = fmaxf(mrun[0], ml0), mn1 = fmaxf(mrun[1], ml1);
        float sc0 = __expf(mrun[0] - mn0), sc1 = __expf(mrun[1] - mn1);
        mrun[0] = mn0; mrun[1] = mn1;
        float ps0 = 0.f, ps1 = 0.f;
        #pragma unroll
        for (int u = 0; u < 8; u++) {
            st[u][0] = __expf(st[u][0] - mn0); ps0 += st[u][0];
            st[u][1] = __expf(st[u][1] - mn0); ps0 += st[u][1];
            st[u][2] = __expf(st[u][2] - mn1); ps1 += st[u][2];
            st[u][3] = __expf(st[u][3] - mn1); ps1 += st[u][3];
        }
        #pragma unroll
        for (int off = 1; off <= 2; off <<= 1) {
            ps0 += __shfl_xor_sync(0xffffffffu, ps0, off);
            ps1 += __shfl_xor_sync(0xffffffffu, ps1, off);
        }
        lrun[0] = lrun[0] * sc0 + ps0;
        lrun[1] = lrun[1] * sc1 + ps1;
        #pragma unroll
        for (int u = 0; u < 8; u++) {
            o[u][0] *= sc0; o[u][1] *= sc0;
            o[u][2] *= sc1; o[u][3] *= sc1;
        }

        // ---- O += P V : P in regs (C-frag -> A-frag), 3 pairings ----
        #pragma unroll
        for (int j = 0; j < 4; j++) {
            uint32_t ah[4], al[4];
            hilo2(st[2*j][0],   st[2*j][1],   ah[0], al[0]);
            hilo2(st[2*j][2],   st[2*j][3],   ah[1], al[1]);
            hilo2(st[2*j+1][0], st[2*j+1][1], ah[2], al[2]);
            hilo2(st[2*j+1][2], st[2*j+1][3], ah[3], al[3]);
            #pragma unroll
            for (int u = 0; u < 4; u++) {
                uint32_t bh[4], bl[4];
                const __nv_bfloat16* vrow = &sm->Vs[j * 16 + (lane & 15)][0];
                ldsm4t(bh, vrow + u * 16 + (lane >> 4) * 8);
                ldsm4t(bl, vrow + 64 + u * 16 + (lane >> 4) * 8);
                mma_bf16(o[2 * u],     ah, bh[0], bh[1]);   // Ph*Vh
                mma_bf16(o[2 * u + 1], ah, bh[2], bh[3]);
                mma_bf16(o[2 * u],     ah, bl[0], bl[1]);   // Ph*Vl
                mma_bf16(o[2 * u + 1], ah, bl[2], bl[3]);
                mma_bf16(o[2 * u],     al, bh[0], bh[1]);   // Pl*Vh
                mma_bf16(o[2 * u + 1], al, bh[2], bh[3]);
            }
        }
    }

    // ---- epilogue: normalize, write [b, s, h*64 + d] ----
    float inv0 = 1.f / lrun[0], inv1 = 1.f / lrun[1];
    int row0 = i0 + qlo;
    #pragma unroll
    for (int u = 0; u < 8; u++) {
        int d = h * CDK + u * 8 + 2 * tq;
        float* p0 = g_AO + ((size_t)b * CS + row0) * CD + d;
        *(float2*)p0            = make_float2(o[u][0] * inv0, o[u][1] * inv0);
        *(float2*)(p0 + 8 * CD) = make_float2(o[u][2] * inv1, o[u][3] * inv1);
    }
}

// ---------------- launch -----------------------------------------------------
extern "C" void kernel_launch(void* const* d_in, const int* in_sizes, int n_in,
                              void* d_out, int out_size)
{
    (void)in_sizes; (void)n_in; (void)out_size;
    const float* X  = (const float*)d_in[0];
    const float* Wq = (const float*)d_in[1];
    const float* Wk = (const float*)d_in[2];
    const float* Wv = (const float*)d_in[3];
    const float* Wo = (const float*)d_in[4];
    const float* rb = (const float*)d_in[5];
    float* out = (float*)d_out;

    // 1) relative-position bias table
    {
        int total = CH * BIAS_LEN;
        bias_table_kernel<<<(total + 255) / 256, 256>>>(rb);
    }
    // 2) fused QKV projections
    {
        dim3 grid(CD / 128, (CB * CS) / 128, 3);
        qkv_kernel<<<grid, 256>>>(X, Wq, Wk, Wv);
    }
    // 3) fused flash attention
    {
        cudaFuncSetAttribute(attn_kernel,
                             cudaFuncAttributeMaxDynamicSharedMemorySize,
                             (int)sizeof(AttnSmem));
        dim3 grid(CS / AQ, CH, CB);
        attn_kernel<<<grid, 256, sizeof(AttnSmem)>>>();
    }
    // 4) output projection -> d_out
    {
        dim3 grid(CD / 128, (CB * CS) / 128);
        out_proj_kernel<<<grid, 256>>>(Wo, out);
    }
}